// round 5
// baseline (speedup 1.0000x reference)
#include <cuda_runtime.h>
#include <cuda_bf16.h>
#include <float.h>
#include <stdint.h>

// Problem constants
#define BB     2
#define SS     2048
#define DD     2048
#define HH     16
#define HDIM   128
#define WINDOW 256
#define MROWS  (BB * SS)   // 4096
#define MD     ((long)MROWS * DD)

// ---------------------------------------------------------------------------
// Scratch (device globals — no allocation allowed)
// ---------------------------------------------------------------------------
__device__ float g_qkv[3 * MROWS * DD];     // q | k | v
__device__ float g_ao [MROWS * DD];
__device__ __nv_bfloat16 g_ahi[MROWS * DD];
__device__ __nv_bfloat16 g_alo[MROWS * DD];
__device__ __nv_bfloat16 g_whi[3 * DD * DD];  // packed Wq|Wk|Wv (slot0 reused for Wo)
__device__ __nv_bfloat16 g_wlo[3 * DD * DD];

// ---------------------------------------------------------------------------
// PTX helpers (family-wide only: harness emits compute_103 PTX -> no tcgen05)
// ---------------------------------------------------------------------------
__device__ __forceinline__ uint32_t smem_u32(const void* p) {
    uint32_t a;
    asm("{ .reg .u64 t; cvta.to.shared.u64 t, %1; cvt.u32.u64 %0, t; }"
        : "=r"(a) : "l"(p));
    return a;
}

#define CP16(dst, src) \
    asm volatile("cp.async.cg.shared.global [%0], [%1], 16;" :: "r"(dst), "l"(src))
#define CP_COMMIT() asm volatile("cp.async.commit_group;" ::: "memory")
#define CP_WAIT1()  asm volatile("cp.async.wait_group 1;" ::: "memory")

#define LDSM_X4(r0, r1, r2, r3, addr) \
    asm volatile("ldmatrix.sync.aligned.m8n8.x4.shared.b16 {%0,%1,%2,%3}, [%4];" \
        : "=r"(r0), "=r"(r1), "=r"(r2), "=r"(r3) : "r"(addr))

#define MMA16816(d, a, b) \
    asm volatile("mma.sync.aligned.m16n8k16.row.col.f32.bf16.bf16.f32 " \
        "{%0,%1,%2,%3}, {%4,%5,%6,%7}, {%8,%9}, {%0,%1,%2,%3};" \
        : "+f"((d)[0]), "+f"((d)[1]), "+f"((d)[2]), "+f"((d)[3]) \
        : "r"((a)[0]), "r"((a)[1]), "r"((a)[2]), "r"((a)[3]), \
          "r"((b)[0]), "r"((b)[1]))

// ---------------------------------------------------------------------------
// Split fp32 -> bf16 hi + lo (grid-stride over float4)
// ---------------------------------------------------------------------------
__global__ __launch_bounds__(256) void split_kernel(
    const float* __restrict__ X, __nv_bfloat16* __restrict__ H,
    __nv_bfloat16* __restrict__ L, int n4)
{
    int i = blockIdx.x * blockDim.x + threadIdx.x;
    if (i >= n4) return;
    float4 x = ((const float4*)X)[i];
    __nv_bfloat16 h0 = __float2bfloat16(x.x);
    __nv_bfloat16 h1 = __float2bfloat16(x.y);
    __nv_bfloat16 h2 = __float2bfloat16(x.z);
    __nv_bfloat16 h3 = __float2bfloat16(x.w);
    __nv_bfloat16 l0 = __float2bfloat16(x.x - __bfloat162float(h0));
    __nv_bfloat16 l1 = __float2bfloat16(x.y - __bfloat162float(h1));
    __nv_bfloat16 l2 = __float2bfloat16(x.z - __bfloat162float(h2));
    __nv_bfloat16 l3 = __float2bfloat16(x.w - __bfloat162float(h3));
    ((__nv_bfloat162*)H)[2*i]   = __nv_bfloat162(h0, h1);
    ((__nv_bfloat162*)H)[2*i+1] = __nv_bfloat162(h2, h3);
    ((__nv_bfloat162*)L)[2*i]   = __nv_bfloat162(l0, l1);
    ((__nv_bfloat162*)L)[2*i+1] = __nv_bfloat162(l2, l3);
}

// ---------------------------------------------------------------------------
// W [K][N] fp32 -> transposed + split: TH/TL [N][K] bf16.  blockIdx.z picks
// the weight matrix (fused Wq/Wk/Wv prep) and its output slot.
// ---------------------------------------------------------------------------
__global__ __launch_bounds__(256) void wsplit3_kernel(
    const float* __restrict__ W0, const float* __restrict__ W1,
    const float* __restrict__ W2,
    __nv_bfloat16* __restrict__ TH, __nv_bfloat16* __restrict__ TL)
{
    __shared__ float t[32][33];
    const float* W = (blockIdx.z == 0) ? W0 : (blockIdx.z == 1) ? W1 : W2;
    __nv_bfloat16* th = TH + (long)blockIdx.z * DD * DD;
    __nv_bfloat16* tl = TL + (long)blockIdx.z * DD * DD;
    const int n0 = blockIdx.x * 32, k0 = blockIdx.y * 32;
    const int tx = threadIdx.x & 31, ty = threadIdx.x >> 5;  // ty 0..7
    #pragma unroll
    for (int i = 0; i < 32; i += 8)
        t[ty + i][tx] = W[(long)(k0 + ty + i) * DD + n0 + tx];
    __syncthreads();
    #pragma unroll
    for (int i = 0; i < 32; i += 8) {
        float x = t[tx][ty + i];             // = W[k0+tx][n0+ty+i]
        long o = (long)(n0 + ty + i) * DD + k0 + tx;
        __nv_bfloat16 h = __float2bfloat16(x);
        th[o] = h;
        tl[o] = __float2bfloat16(x - __bfloat162float(h));
    }
}

// ---------------------------------------------------------------------------
// bf16x3 HMMA GEMM with packed-N weights (unchanged — at the measured
// HMMA-fallback MAC ceiling).
// ---------------------------------------------------------------------------
#define GKB      64
#define GNIT     96                       // 3 passes * 32 k-blocks
#define GPAD     72                       // row stride in bf16 elems (144B)
#define G_OPB    (128 * GPAD * 2)         // 18432 B per operand
#define G_STAGEB (2 * G_OPB)              // 36864 B
#define GSMEM_TOTAL (3 * G_STAGEB)        // 110592 B

__device__ __forceinline__ void g_load_stage(
    uint32_t sbase, int stage, int tid,
    const __nv_bfloat16* __restrict__ Asrc, const __nv_bfloat16* __restrict__ Bsrc,
    long row0, long bcol0, int kc)
{
    const uint32_t abase = sbase + stage * G_STAGEB;
    const uint32_t bbase = abase + G_OPB;
    const __nv_bfloat16* Ap = Asrc + row0 * DD + kc;
    const __nv_bfloat16* Bp = Bsrc + bcol0 * DD + kc;
    #pragma unroll
    for (int i = 0; i < 4; i++) {
        int idx = i * 256 + tid;
        int r  = idx >> 3;                 // 0..127
        int ch = idx & 7;                  // 16B chunk within 128B of row data
        uint32_t so = (uint32_t)(r * (GPAD * 2) + ch * 16);
        CP16(abase + so, Ap + (long)r * DD + ch * 8);
        CP16(bbase + so, Bp + (long)r * DD + ch * 8);
    }
}

__global__ __launch_bounds__(256, 2) void gemm_bf16x3_kernel(
    const __nv_bfloat16* __restrict__ Ahi, const __nv_bfloat16* __restrict__ Alo,
    const __nv_bfloat16* __restrict__ Bhi, const __nv_bfloat16* __restrict__ Blo,
    const float* __restrict__ bias, float* __restrict__ Cbase)
{
    extern __shared__ char gsm[];
    const uint32_t sb = smem_u32(gsm);
    const int tid  = threadIdx.x;
    const int wid  = tid >> 5;
    const int lane = tid & 31;
    const long bcol0 = (long)blockIdx.x * 128;       // packed-weight row offset
    const long row0  = (long)blockIdx.y * 128;
    const int  which = (int)(bcol0 >> 11);           // 0..2
    const long cc0   = bcol0 & 2047;                 // column within output
    float* C = Cbase + (long)which * MD;

    const int warp_m = (wid >> 1) * 32;
    const int warp_n = (wid & 1) * 64;
    const int lr = lane & 15;
    const int hl = lane >> 4;

    float acc[2][8][4];
    #pragma unroll
    for (int mt = 0; mt < 2; mt++)
        #pragma unroll
        for (int nt = 0; nt < 8; nt++)
            #pragma unroll
            for (int e = 0; e < 4; e++)
                acc[mt][nt][e] = 0.0f;

    g_load_stage(sb, 0, tid, Ahi, Bhi, row0, bcol0, 0);
    CP_COMMIT();
    g_load_stage(sb, 1, tid, Ahi, Bhi, row0, bcol0, GKB);
    CP_COMMIT();

    int s = 0, ps = 2;
    #pragma unroll 1
    for (int it = 0; it < GNIT; it++) {
        CP_WAIT1();
        __syncthreads();

        const int nit = it + 2;
        if (nit < GNIT) {
            const int pass = nit >> 5;
            const int kc = (nit & 31) * GKB;
            const __nv_bfloat16* As = (pass == 2) ? Alo : Ahi;
            const __nv_bfloat16* Bs = (pass == 1) ? Blo : Bhi;
            g_load_stage(sb, ps, tid, As, Bs, row0, bcol0, kc);
        }
        CP_COMMIT();

        const uint32_t sA = sb + s * G_STAGEB;
        const uint32_t sB = sA + G_OPB;
        #pragma unroll
        for (int ks = 0; ks < 4; ks++) {
            const int k0 = ks * 16;
            uint32_t aF[2][4], bF[8][2];
            #pragma unroll
            for (int mt = 0; mt < 2; mt++) {
                uint32_t addr = sA + (uint32_t)((warp_m + mt * 16 + lr) * (GPAD * 2)
                                              + (k0 + 8 * hl) * 2);
                LDSM_X4(aF[mt][0], aF[mt][1], aF[mt][2], aF[mt][3], addr);
            }
            #pragma unroll
            for (int nt2 = 0; nt2 < 4; nt2++) {
                uint32_t r0, r1, r2, r3;
                uint32_t addr = sB + (uint32_t)((warp_n + nt2 * 16 + lr) * (GPAD * 2)
                                              + (k0 + 8 * hl) * 2);
                LDSM_X4(r0, r1, r2, r3, addr);
                bF[2 * nt2][0]     = r0;
                bF[2 * nt2 + 1][0] = r1;
                bF[2 * nt2][1]     = r2;
                bF[2 * nt2 + 1][1] = r3;
            }
            #pragma unroll
            for (int mt = 0; mt < 2; mt++)
                #pragma unroll
                for (int nt = 0; nt < 8; nt++)
                    MMA16816(acc[mt][nt], aF[mt], bF[nt]);
        }
        s = (s == 2) ? 0 : s + 1;
        ps = (ps == 2) ? 0 : ps + 1;
    }

    const int erow = lane >> 2;
    const int ecol = (lane & 3) * 2;
    #pragma unroll
    for (int mt = 0; mt < 2; mt++) {
        #pragma unroll
        for (int nt = 0; nt < 8; nt++) {
            const long r  = row0 + warp_m + mt * 16 + erow;
            const long cc = cc0 + warp_n + nt * 8 + ecol;
            float b0 = bias ? bias[cc] : 0.0f;
            float b1 = bias ? bias[cc + 1] : 0.0f;
            float2 v0 = make_float2(acc[mt][nt][0] + b0, acc[mt][nt][1] + b1);
            float2 v1 = make_float2(acc[mt][nt][2] + b0, acc[mt][nt][3] + b1);
            *(float2*)(C + r * DD + cc)       = v0;
            *(float2*)(C + (r + 8) * DD + cc) = v1;
        }
    }
}

// ---------------------------------------------------------------------------
// Local-window attention (flash-style, fp32).
// SMEM cut to 82944 B (2 CTAs/SM):
//   Qs [128][65]  — K/V overlay union buffer:
//   KV [128*65]   K d-major [128][65] during QK; V [64][128] during PV
//   PsT[64][64]   rotation-swizzled: key row kr (=4c+j) holds the float4 for
//                 qrows 4r..4r+3 at word kr*64 + ((4r + 4*(kr>>2)) & 63)
//                 -> 2-way write conflicts instead of 16-way; reads broadcast.
// Epilogue emits fp32 O plus bf16 hi/lo split (feeds Wo gemm).
// ---------------------------------------------------------------------------
#define BQ   64
#define BKC  64
#define ATT_SMEM_BYTES ((128*65 + 128*65 + 64*64) * 4)   // 82944

__global__ __launch_bounds__(256, 2) void attn_local_kernel(
    const float* __restrict__ Q, const float* __restrict__ K,
    const float* __restrict__ V, const int* __restrict__ amask,
    float* __restrict__ O,
    __nv_bfloat16* __restrict__ OH, __nv_bfloat16* __restrict__ OL)
{
    const int q0 = blockIdx.x * BQ;
    const int h  = blockIdx.y;
    const int b  = blockIdx.z;

    extern __shared__ float sm[];
    float* Qs  = sm;                      // [128][65] d-major
    float* KV  = Qs + 128 * 65;           // union buffer
    float* PsT = KV + 128 * 65;           // [64][64] rotated

    const int tid = threadIdx.x;
    const int r   = tid >> 4;             // 0..15 -> q rows r*4..r*4+3
    const int c   = tid & 15;

    const float* qbase = Q + ((long)(b * SS + q0)) * DD + h * HDIM;
    for (int e = tid; e < BQ * HDIM; e += 256) {
        int qi = e >> 7, d = e & 127;
        Qs[d * 65 + qi] = qbase[(long)qi * DD + d];
    }

    float m[4], l[4], o[4][8];
    #pragma unroll
    for (int i = 0; i < 4; i++) {
        m[i] = -FLT_MAX; l[i] = 0.0f;
        #pragma unroll
        for (int dd = 0; dd < 8; dd++) o[i][dd] = 0.0f;
    }

    for (int t = 0; t < 5; t++) {
        const int kb = q0 - WINDOW + t * BKC;
        if (kb < 0) continue;

        __syncthreads();   // prev PV done reading KV/PsT (1st iter: Q ready)

        const float* kbase = K + ((long)(b * SS + kb)) * DD + h * HDIM;
        for (int e = tid; e < BKC * HDIM; e += 256) {
            int kj = e >> 7, d = e & 127;
            KV[d * 65 + kj] = kbase[(long)kj * DD + d];
        }
        __syncthreads();   // K ready

        float s[4][4];
        #pragma unroll
        for (int i = 0; i < 4; i++)
            #pragma unroll
            for (int j = 0; j < 4; j++) s[i][j] = 0.0f;

        for (int d = 0; d < HDIM; d++) {
            float qv[4], kv[4];
            #pragma unroll
            for (int i = 0; i < 4; i++) qv[i] = Qs[d * 65 + r * 4 + i];
            #pragma unroll
            for (int j = 0; j < 4; j++) kv[j] = KV[d * 65 + c * 4 + j];
            #pragma unroll
            for (int i = 0; i < 4; i++)
                #pragma unroll
                for (int j = 0; j < 4; j++)
                    s[i][j] = fmaf(qv[i], kv[j], s[i][j]);
        }

        float scl[4];
        #pragma unroll
        for (int i = 0; i < 4; i++) {
            const int qi = q0 + r * 4 + i;
            #pragma unroll
            for (int j = 0; j < 4; j++) {
                const int kj = kb + c * 4 + j;
                bool ok = (kj <= qi) && (kj > qi - WINDOW) && (amask[b * SS + kj] > 0);
                if (!ok) s[i][j] = -FLT_MAX;
            }
            float mx = fmaxf(fmaxf(s[i][0], s[i][1]), fmaxf(s[i][2], s[i][3]));
            #pragma unroll
            for (int w = 1; w <= 8; w <<= 1)
                mx = fmaxf(mx, __shfl_xor_sync(0xffffffffu, mx, w));

            float mnew = fmaxf(m[i], mx);
            scl[i] = __expf(m[i] - mnew);
            m[i] = mnew;

            float sum = 0.0f;
            #pragma unroll
            for (int j = 0; j < 4; j++) {
                float p = (s[i][j] > -1e37f) ? __expf(s[i][j] - mnew) : 0.0f;
                s[i][j] = p;
                sum += p;
            }
            #pragma unroll
            for (int w = 1; w <= 8; w <<= 1)
                sum += __shfl_xor_sync(0xffffffffu, sum, w);

            l[i] = l[i] * scl[i] + sum;
            #pragma unroll
            for (int dd = 0; dd < 8; dd++) o[i][dd] *= scl[i];
        }

        #pragma unroll
        for (int j = 0; j < 4; j++) {
            int row  = c * 4 + j;
            int wcol = (4 * r + 4 * c) & 63;
            *(float4*)&PsT[row * 64 + wcol] =
                make_float4(s[0][j], s[1][j], s[2][j], s[3][j]);
        }
        __syncthreads();   // K reads done + PsT written -> safe to load V over K

        const float* vbase = V + ((long)(b * SS + kb)) * DD + h * HDIM;
        for (int e = tid; e < BKC * HDIM; e += 256) {
            int kj = e >> 7, d = e & 127;
            KV[kj * 128 + d] = vbase[(long)kj * DD + d];
        }
        __syncthreads();   // V ready

        #pragma unroll 8
        for (int j = 0; j < BKC; j++) {
            int wcol = (4 * r + 4 * (j >> 2)) & 63;
            float4 p4 = *(const float4*)&PsT[j * 64 + wcol];
            float4 va = *(const float4*)&KV[j * 128 + c * 8];
            float4 vb = *(const float4*)&KV[j * 128 + c * 8 + 4];
            const float pv[4] = {p4.x, p4.y, p4.z, p4.w};
            const float vv[8] = {va.x, va.y, va.z, va.w, vb.x, vb.y, vb.z, vb.w};
            #pragma unroll
            for (int i = 0; i < 4; i++)
                #pragma unroll
                for (int dd = 0; dd < 8; dd++)
                    o[i][dd] = fmaf(pv[i], vv[dd], o[i][dd]);
        }
    }

    #pragma unroll
    for (int i = 0; i < 4; i++) {
        const int row = q0 + r * 4 + i;
        const float inv = 1.0f / l[i];
        const long base = ((long)(b * SS + row)) * DD + h * HDIM + c * 8;
        float out[8];
        #pragma unroll
        for (int dd = 0; dd < 8; dd++) out[dd] = o[i][dd] * inv;
        *(float4*)(O + base)     = make_float4(out[0], out[1], out[2], out[3]);
        *(float4*)(O + base + 4) = make_float4(out[4], out[5], out[6], out[7]);
        #pragma unroll
        for (int p2 = 0; p2 < 4; p2++) {
            __nv_bfloat16 h0 = __float2bfloat16(out[2*p2]);
            __nv_bfloat16 h1 = __float2bfloat16(out[2*p2+1]);
            __nv_bfloat16 l0 = __float2bfloat16(out[2*p2]   - __bfloat162float(h0));
            __nv_bfloat16 l1 = __float2bfloat16(out[2*p2+1] - __bfloat162float(h1));
            *(__nv_bfloat162*)(OH + base + 2*p2) = __nv_bfloat162(h0, h1);
            *(__nv_bfloat162*)(OL + base + 2*p2) = __nv_bfloat162(l0, l1);
        }
    }
}

// ---------------------------------------------------------------------------
// Launch
// ---------------------------------------------------------------------------
extern "C" void kernel_launch(void* const* d_in, const int* in_sizes, int n_in,
                              void* d_out, int out_size)
{
    const float* hs    = (const float*)d_in[0];
    const int*   amask = (const int*)  d_in[1];
    const float* Wq    = (const float*)d_in[2];
    const float* Wk    = (const float*)d_in[3];
    const float* Wv    = (const float*)d_in[4];
    const float* Wo    = (const float*)d_in[5];
    const float* bo    = (const float*)d_in[6];
    float*       out   = (float*)d_out;

    float *qkv, *ao;
    __nv_bfloat16 *ahi, *alo, *whi, *wlo;
    cudaGetSymbolAddress((void**)&qkv, g_qkv);
    cudaGetSymbolAddress((void**)&ao,  g_ao);
    cudaGetSymbolAddress((void**)&ahi, g_ahi);
    cudaGetSymbolAddress((void**)&alo, g_alo);
    cudaGetSymbolAddress((void**)&whi, g_whi);
    cudaGetSymbolAddress((void**)&wlo, g_wlo);

    cudaFuncSetAttribute(gemm_bf16x3_kernel,
                         cudaFuncAttributeMaxDynamicSharedMemorySize, GSMEM_TOTAL);
    cudaFuncSetAttribute(attn_local_kernel,
                         cudaFuncAttributeMaxDynamicSharedMemorySize, ATT_SMEM_BYTES);

    const int n4 = MROWS * DD / 4;

    split_kernel<<<(n4 + 255) / 256, 256>>>(hs, ahi, alo, n4);
    dim3 wgrid3(DD / 32, DD / 32, 3);
    wsplit3_kernel<<<wgrid3, 256>>>(Wq, Wk, Wv, whi, wlo);

    dim3 qkvgrid(3 * DD / 128, MROWS / 128);    // (48, 32)
    gemm_bf16x3_kernel<<<qkvgrid, 256, GSMEM_TOTAL>>>(ahi, alo, whi, wlo, nullptr, qkv);

    dim3 wgrid1(DD / 32, DD / 32, 1);
    wsplit3_kernel<<<wgrid1, 256>>>(Wo, Wo, Wo, whi, wlo);

    dim3 attn_grid(SS / BQ, HH, BB);            // (32, 16, 2)
    attn_local_kernel<<<attn_grid, 256, ATT_SMEM_BYTES>>>(
        qkv, qkv + MD, qkv + 2 * MD, amask, ao, ahi, alo);

    dim3 ogrid(DD / 128, MROWS / 128);          // (16, 32)
    gemm_bf16x3_kernel<<<ogrid, 256, GSMEM_TOTAL>>>(ahi, alo, whi, wlo, bo, out);
}

// round 6
// speedup vs baseline: 1.0132x; 1.0132x over previous
#include <cuda_runtime.h>
#include <cuda_bf16.h>
#include <float.h>
#include <stdint.h>

// Problem constants
#define BB     2
#define SS     2048
#define DD     2048
#define HH     16
#define HDIM   128
#define WINDOW 256
#define MROWS  (BB * SS)   // 4096
#define MD     ((long)MROWS * DD)

// ---------------------------------------------------------------------------
// Scratch (device globals — no allocation allowed)
// ---------------------------------------------------------------------------
__device__ float g_qkv[3 * MROWS * DD];     // q | k | v
__device__ float g_ao [MROWS * DD];
__device__ __nv_bfloat16 g_ahi[MROWS * DD];
__device__ __nv_bfloat16 g_alo[MROWS * DD];
__device__ __nv_bfloat16 g_whi[3 * DD * DD];  // packed Wq|Wk|Wv (slot0 reused for Wo)
__device__ __nv_bfloat16 g_wlo[3 * DD * DD];

// ---------------------------------------------------------------------------
// PTX helpers (family-wide only: harness emits compute_103 PTX -> no tcgen05)
// ---------------------------------------------------------------------------
__device__ __forceinline__ uint32_t smem_u32(const void* p) {
    uint32_t a;
    asm("{ .reg .u64 t; cvta.to.shared.u64 t, %1; cvt.u32.u64 %0, t; }"
        : "=r"(a) : "l"(p));
    return a;
}

#define CP16(dst, src) \
    asm volatile("cp.async.cg.shared.global [%0], [%1], 16;" :: "r"(dst), "l"(src))
#define CP_COMMIT() asm volatile("cp.async.commit_group;" ::: "memory")
#define CP_WAIT1()  asm volatile("cp.async.wait_group 1;" ::: "memory")

#define LDSM_X4(r0, r1, r2, r3, addr) \
    asm volatile("ldmatrix.sync.aligned.m8n8.x4.shared.b16 {%0,%1,%2,%3}, [%4];" \
        : "=r"(r0), "=r"(r1), "=r"(r2), "=r"(r3) : "r"(addr))

#define MMA16816(d, a, b) \
    asm volatile("mma.sync.aligned.m16n8k16.row.col.f32.bf16.bf16.f32 " \
        "{%0,%1,%2,%3}, {%4,%5,%6,%7}, {%8,%9}, {%0,%1,%2,%3};" \
        : "+f"((d)[0]), "+f"((d)[1]), "+f"((d)[2]), "+f"((d)[3]) \
        : "r"((a)[0]), "r"((a)[1]), "r"((a)[2]), "r"((a)[3]), \
          "r"((b)[0]), "r"((b)[1]))

// ---------------------------------------------------------------------------
// Split fp32 -> bf16 hi + lo (grid-stride over float4)
// ---------------------------------------------------------------------------
__global__ __launch_bounds__(256) void split_kernel(
    const float* __restrict__ X, __nv_bfloat16* __restrict__ H,
    __nv_bfloat16* __restrict__ L, int n4)
{
    int i = blockIdx.x * blockDim.x + threadIdx.x;
    if (i >= n4) return;
    float4 x = ((const float4*)X)[i];
    __nv_bfloat16 h0 = __float2bfloat16(x.x);
    __nv_bfloat16 h1 = __float2bfloat16(x.y);
    __nv_bfloat16 h2 = __float2bfloat16(x.z);
    __nv_bfloat16 h3 = __float2bfloat16(x.w);
    __nv_bfloat16 l0 = __float2bfloat16(x.x - __bfloat162float(h0));
    __nv_bfloat16 l1 = __float2bfloat16(x.y - __bfloat162float(h1));
    __nv_bfloat16 l2 = __float2bfloat16(x.z - __bfloat162float(h2));
    __nv_bfloat16 l3 = __float2bfloat16(x.w - __bfloat162float(h3));
    ((__nv_bfloat162*)H)[2*i]   = __nv_bfloat162(h0, h1);
    ((__nv_bfloat162*)H)[2*i+1] = __nv_bfloat162(h2, h3);
    ((__nv_bfloat162*)L)[2*i]   = __nv_bfloat162(l0, l1);
    ((__nv_bfloat162*)L)[2*i+1] = __nv_bfloat162(l2, l3);
}

// ---------------------------------------------------------------------------
// W [K][N] fp32 -> transposed + split: TH/TL [N][K] bf16.  blockIdx.z picks
// the weight matrix (fused Wq/Wk/Wv prep) and its output slot.
// ---------------------------------------------------------------------------
__global__ __launch_bounds__(256) void wsplit3_kernel(
    const float* __restrict__ W0, const float* __restrict__ W1,
    const float* __restrict__ W2,
    __nv_bfloat16* __restrict__ TH, __nv_bfloat16* __restrict__ TL)
{
    __shared__ float t[32][33];
    const float* W = (blockIdx.z == 0) ? W0 : (blockIdx.z == 1) ? W1 : W2;
    __nv_bfloat16* th = TH + (long)blockIdx.z * DD * DD;
    __nv_bfloat16* tl = TL + (long)blockIdx.z * DD * DD;
    const int n0 = blockIdx.x * 32, k0 = blockIdx.y * 32;
    const int tx = threadIdx.x & 31, ty = threadIdx.x >> 5;  // ty 0..7
    #pragma unroll
    for (int i = 0; i < 32; i += 8)
        t[ty + i][tx] = W[(long)(k0 + ty + i) * DD + n0 + tx];
    __syncthreads();
    #pragma unroll
    for (int i = 0; i < 32; i += 8) {
        float x = t[tx][ty + i];             // = W[k0+tx][n0+ty+i]
        long o = (long)(n0 + ty + i) * DD + k0 + tx;
        __nv_bfloat16 h = __float2bfloat16(x);
        th[o] = h;
        tl[o] = __float2bfloat16(x - __bfloat162float(h));
    }
}

// ---------------------------------------------------------------------------
// bf16x3 HMMA GEMM with packed-N weights (unchanged — at the measured
// mma.sync MAC ceiling).
// ---------------------------------------------------------------------------
#define GKB      64
#define GNIT     96                       // 3 passes * 32 k-blocks
#define GPAD     72                       // row stride in bf16 elems (144B)
#define G_OPB    (128 * GPAD * 2)         // 18432 B per operand
#define G_STAGEB (2 * G_OPB)              // 36864 B
#define GSMEM_TOTAL (3 * G_STAGEB)        // 110592 B

__device__ __forceinline__ void g_load_stage(
    uint32_t sbase, int stage, int tid,
    const __nv_bfloat16* __restrict__ Asrc, const __nv_bfloat16* __restrict__ Bsrc,
    long row0, long bcol0, int kc)
{
    const uint32_t abase = sbase + stage * G_STAGEB;
    const uint32_t bbase = abase + G_OPB;
    const __nv_bfloat16* Ap = Asrc + row0 * DD + kc;
    const __nv_bfloat16* Bp = Bsrc + bcol0 * DD + kc;
    #pragma unroll
    for (int i = 0; i < 4; i++) {
        int idx = i * 256 + tid;
        int r  = idx >> 3;                 // 0..127
        int ch = idx & 7;                  // 16B chunk within 128B of row data
        uint32_t so = (uint32_t)(r * (GPAD * 2) + ch * 16);
        CP16(abase + so, Ap + (long)r * DD + ch * 8);
        CP16(bbase + so, Bp + (long)r * DD + ch * 8);
    }
}

__global__ __launch_bounds__(256, 2) void gemm_bf16x3_kernel(
    const __nv_bfloat16* __restrict__ Ahi, const __nv_bfloat16* __restrict__ Alo,
    const __nv_bfloat16* __restrict__ Bhi, const __nv_bfloat16* __restrict__ Blo,
    const float* __restrict__ bias, float* __restrict__ Cbase)
{
    extern __shared__ char gsm[];
    const uint32_t sb = smem_u32(gsm);
    const int tid  = threadIdx.x;
    const int wid  = tid >> 5;
    const int lane = tid & 31;
    const long bcol0 = (long)blockIdx.x * 128;       // packed-weight row offset
    const long row0  = (long)blockIdx.y * 128;
    const int  which = (int)(bcol0 >> 11);           // 0..2
    const long cc0   = bcol0 & 2047;                 // column within output
    float* C = Cbase + (long)which * MD;

    const int warp_m = (wid >> 1) * 32;
    const int warp_n = (wid & 1) * 64;
    const int lr = lane & 15;
    const int hl = lane >> 4;

    float acc[2][8][4];
    #pragma unroll
    for (int mt = 0; mt < 2; mt++)
        #pragma unroll
        for (int nt = 0; nt < 8; nt++)
            #pragma unroll
            for (int e = 0; e < 4; e++)
                acc[mt][nt][e] = 0.0f;

    g_load_stage(sb, 0, tid, Ahi, Bhi, row0, bcol0, 0);
    CP_COMMIT();
    g_load_stage(sb, 1, tid, Ahi, Bhi, row0, bcol0, GKB);
    CP_COMMIT();

    int s = 0, ps = 2;
    #pragma unroll 1
    for (int it = 0; it < GNIT; it++) {
        CP_WAIT1();
        __syncthreads();

        const int nit = it + 2;
        if (nit < GNIT) {
            const int pass = nit >> 5;
            const int kc = (nit & 31) * GKB;
            const __nv_bfloat16* As = (pass == 2) ? Alo : Ahi;
            const __nv_bfloat16* Bs = (pass == 1) ? Blo : Bhi;
            g_load_stage(sb, ps, tid, As, Bs, row0, bcol0, kc);
        }
        CP_COMMIT();

        const uint32_t sA = sb + s * G_STAGEB;
        const uint32_t sB = sA + G_OPB;
        #pragma unroll
        for (int ks = 0; ks < 4; ks++) {
            const int k0 = ks * 16;
            uint32_t aF[2][4], bF[8][2];
            #pragma unroll
            for (int mt = 0; mt < 2; mt++) {
                uint32_t addr = sA + (uint32_t)((warp_m + mt * 16 + lr) * (GPAD * 2)
                                              + (k0 + 8 * hl) * 2);
                LDSM_X4(aF[mt][0], aF[mt][1], aF[mt][2], aF[mt][3], addr);
            }
            #pragma unroll
            for (int nt2 = 0; nt2 < 4; nt2++) {
                uint32_t r0, r1, r2, r3;
                uint32_t addr = sB + (uint32_t)((warp_n + nt2 * 16 + lr) * (GPAD * 2)
                                              + (k0 + 8 * hl) * 2);
                LDSM_X4(r0, r1, r2, r3, addr);
                bF[2 * nt2][0]     = r0;
                bF[2 * nt2 + 1][0] = r1;
                bF[2 * nt2][1]     = r2;
                bF[2 * nt2 + 1][1] = r3;
            }
            #pragma unroll
            for (int mt = 0; mt < 2; mt++)
                #pragma unroll
                for (int nt = 0; nt < 8; nt++)
                    MMA16816(acc[mt][nt], aF[mt], bF[nt]);
        }
        s = (s == 2) ? 0 : s + 1;
        ps = (ps == 2) ? 0 : ps + 1;
    }

    const int erow = lane >> 2;
    const int ecol = (lane & 3) * 2;
    #pragma unroll
    for (int mt = 0; mt < 2; mt++) {
        #pragma unroll
        for (int nt = 0; nt < 8; nt++) {
            const long r  = row0 + warp_m + mt * 16 + erow;
            const long cc = cc0 + warp_n + nt * 8 + ecol;
            float b0 = bias ? bias[cc] : 0.0f;
            float b1 = bias ? bias[cc + 1] : 0.0f;
            float2 v0 = make_float2(acc[mt][nt][0] + b0, acc[mt][nt][1] + b1);
            float2 v1 = make_float2(acc[mt][nt][2] + b0, acc[mt][nt][3] + b1);
            *(float2*)(C + r * DD + cc)       = v0;
            *(float2*)(C + (r + 8) * DD + cc) = v1;
        }
    }
}

// ---------------------------------------------------------------------------
// Local-window attention (flash-style, fp32).
// Round-4 skeleton (PARALLEL K+V chunk loads under one barrier) with the
// LDS-wavefront fixes:
//   Qs[128][68], Ks[128][68]: index-contiguous -> the S-loop does ONE
//     broadcast float4 Q read + ONE conflict-free float4 K read per d
//     (was 8 scalar LDS).  Pad 68 keeps float4 alignment and spreads banks.
//   Vs[64][128] row-major, float4 reads in PV.
//   PsT[64][64] rotation-swizzled (write conflict 16-way -> ~4-way).
// Vectorized float4 global loads for Q/K/V; mask hoisted to one int4/chunk.
// Epilogue emits fp32 O plus bf16 hi/lo split (feeds Wo gemm).
// SMEM: (128*68*2 + 64*128 + 64*64)*4 = 118784 B
// ---------------------------------------------------------------------------
#define BQ   64
#define BKC  64
#define QKPAD 68
#define ATT_SMEM_BYTES ((128*QKPAD*2 + 64*128 + 64*64) * 4)

__global__ __launch_bounds__(256) void attn_local_kernel(
    const float* __restrict__ Q, const float* __restrict__ K,
    const float* __restrict__ V, const int* __restrict__ amask,
    float* __restrict__ O,
    __nv_bfloat16* __restrict__ OH, __nv_bfloat16* __restrict__ OL)
{
    const int q0 = blockIdx.x * BQ;
    const int h  = blockIdx.y;
    const int b  = blockIdx.z;

    extern __shared__ float sm[];
    float* Qs  = sm;                       // [128][68] d-major, qi contiguous
    float* Ks  = Qs + 128 * QKPAD;         // [128][68]
    float* Vs  = Ks + 128 * QKPAD;         // [64][128]
    float* PsT = Vs + 64 * 128;            // [64][64] rotated

    const int tid = threadIdx.x;
    const int r   = tid >> 4;              // 0..15 -> q rows r*4..r*4+3
    const int c   = tid & 15;

    // Q load: float4 over d, transposed store (4 scalar STS per float4)
    const float* qbase = Q + ((long)(b * SS + q0)) * DD + h * HDIM;
    #pragma unroll
    for (int e = tid; e < BQ * (HDIM / 4); e += 256) {
        int qi = e >> 5, d4 = e & 31;
        float4 f = *(const float4*)(qbase + (long)qi * DD + d4 * 4);
        Qs[(d4 * 4 + 0) * QKPAD + qi] = f.x;
        Qs[(d4 * 4 + 1) * QKPAD + qi] = f.y;
        Qs[(d4 * 4 + 2) * QKPAD + qi] = f.z;
        Qs[(d4 * 4 + 3) * QKPAD + qi] = f.w;
    }

    float m[4], l[4], o[4][8];
    #pragma unroll
    for (int i = 0; i < 4; i++) {
        m[i] = -FLT_MAX; l[i] = 0.0f;
        #pragma unroll
        for (int dd = 0; dd < 8; dd++) o[i][dd] = 0.0f;
    }

    for (int t = 0; t < 5; t++) {
        const int kb = q0 - WINDOW + t * BKC;
        if (kb < 0) continue;

        __syncthreads();   // prev chunk's compute done (1st iter: Q ready)

        // K and V loaded together — both gmem loads in flight under one barrier
        const float* kbase = K + ((long)(b * SS + kb)) * DD + h * HDIM;
        const float* vbase = V + ((long)(b * SS + kb)) * DD + h * HDIM;
        #pragma unroll
        for (int e = tid; e < BKC * (HDIM / 4); e += 256) {
            int kj = e >> 5, d4 = e & 31;
            float4 kf = *(const float4*)(kbase + (long)kj * DD + d4 * 4);
            float4 vf = *(const float4*)(vbase + (long)kj * DD + d4 * 4);
            Ks[(d4 * 4 + 0) * QKPAD + kj] = kf.x;
            Ks[(d4 * 4 + 1) * QKPAD + kj] = kf.y;
            Ks[(d4 * 4 + 2) * QKPAD + kj] = kf.z;
            Ks[(d4 * 4 + 3) * QKPAD + kj] = kf.w;
            *(float4*)&Vs[kj * 128 + d4 * 4] = vf;
        }
        // mask for this thread's 4 key columns (int4-aligned: kb, 4c mult of 4)
        const int4 mk4 = *(const int4*)(amask + b * SS + kb + c * 4);
        __syncthreads();   // K/V ready

        // S = Q @ K^T (unscaled): 2 x LDS.128 + 16 FMA per d
        float s[4][4];
        #pragma unroll
        for (int i = 0; i < 4; i++)
            #pragma unroll
            for (int j = 0; j < 4; j++) s[i][j] = 0.0f;

        #pragma unroll 4
        for (int d = 0; d < HDIM; d++) {
            float4 q4 = *(const float4*)&Qs[d * QKPAD + r * 4];
            float4 k4 = *(const float4*)&Ks[d * QKPAD + c * 4];
            const float qv[4] = {q4.x, q4.y, q4.z, q4.w};
            const float kv[4] = {k4.x, k4.y, k4.z, k4.w};
            #pragma unroll
            for (int i = 0; i < 4; i++)
                #pragma unroll
                for (int j = 0; j < 4; j++)
                    s[i][j] = fmaf(qv[i], kv[j], s[i][j]);
        }

        // Mask + online softmax
        const int mok[4] = {mk4.x, mk4.y, mk4.z, mk4.w};
        float scl[4];
        #pragma unroll
        for (int i = 0; i < 4; i++) {
            const int qi = q0 + r * 4 + i;
            #pragma unroll
            for (int j = 0; j < 4; j++) {
                const int kj = kb + c * 4 + j;
                bool ok = (kj <= qi) && (kj > qi - WINDOW) && (mok[j] > 0);
                if (!ok) s[i][j] = -FLT_MAX;
            }
            float mx = fmaxf(fmaxf(s[i][0], s[i][1]), fmaxf(s[i][2], s[i][3]));
            #pragma unroll
            for (int w = 1; w <= 8; w <<= 1)
                mx = fmaxf(mx, __shfl_xor_sync(0xffffffffu, mx, w));

            float mnew = fmaxf(m[i], mx);
            scl[i] = __expf(m[i] - mnew);
            m[i] = mnew;

            float sum = 0.0f;
            #pragma unroll
            for (int j = 0; j < 4; j++) {
                float p = (s[i][j] > -1e37f) ? __expf(s[i][j] - mnew) : 0.0f;
                s[i][j] = p;
                sum += p;
            }
            #pragma unroll
            for (int w = 1; w <= 8; w <<= 1)
                sum += __shfl_xor_sync(0xffffffffu, sum, w);

            l[i] = l[i] * scl[i] + sum;
            #pragma unroll
            for (int dd = 0; dd < 8; dd++) o[i][dd] *= scl[i];
        }

        // Stage P transposed + rotated: key row (4c+j) holds qrows 4r..4r+3
        // at word (4r + 4c) & 63
        #pragma unroll
        for (int j = 0; j < 4; j++) {
            int row  = c * 4 + j;
            int wcol = (4 * r + 4 * c) & 63;
            *(float4*)&PsT[row * 64 + wcol] =
                make_float4(s[0][j], s[1][j], s[2][j], s[3][j]);
        }
        __syncthreads();   // PsT visible

        // O += P @ V  (thread's output cols: c*8..c*8+7)
        #pragma unroll 8
        for (int j = 0; j < BKC; j++) {
            int wcol = (4 * r + 4 * (j >> 2)) & 63;
            float4 p4 = *(const float4*)&PsT[j * 64 + wcol];
            float4 va = *(const float4*)&Vs[j * 128 + c * 8];
            float4 vb = *(const float4*)&Vs[j * 128 + c * 8 + 4];
            const float pv[4] = {p4.x, p4.y, p4.z, p4.w};
            const float vv[8] = {va.x, va.y, va.z, va.w, vb.x, vb.y, vb.z, vb.w};
            #pragma unroll
            for (int i = 0; i < 4; i++)
                #pragma unroll
                for (int dd = 0; dd < 8; dd++)
                    o[i][dd] = fmaf(pv[i], vv[dd], o[i][dd]);
        }
    }

    // Normalize + store fp32 AND bf16 hi/lo split
    #pragma unroll
    for (int i = 0; i < 4; i++) {
        const int row = q0 + r * 4 + i;
        const float inv = 1.0f / l[i];
        const long base = ((long)(b * SS + row)) * DD + h * HDIM + c * 8;
        float out[8];
        #pragma unroll
        for (int dd = 0; dd < 8; dd++) out[dd] = o[i][dd] * inv;
        *(float4*)(O + base)     = make_float4(out[0], out[1], out[2], out[3]);
        *(float4*)(O + base + 4) = make_float4(out[4], out[5], out[6], out[7]);
        #pragma unroll
        for (int p2 = 0; p2 < 4; p2++) {
            __nv_bfloat16 h0 = __float2bfloat16(out[2*p2]);
            __nv_bfloat16 h1 = __float2bfloat16(out[2*p2+1]);
            __nv_bfloat16 l0 = __float2bfloat16(out[2*p2]   - __bfloat162float(h0));
            __nv_bfloat16 l1 = __float2bfloat16(out[2*p2+1] - __bfloat162float(h1));
            *(__nv_bfloat162*)(OH + base + 2*p2) = __nv_bfloat162(h0, h1);
            *(__nv_bfloat162*)(OL + base + 2*p2) = __nv_bfloat162(l0, l1);
        }
    }
}

// ---------------------------------------------------------------------------
// Launch
// ---------------------------------------------------------------------------
extern "C" void kernel_launch(void* const* d_in, const int* in_sizes, int n_in,
                              void* d_out, int out_size)
{
    const float* hs    = (const float*)d_in[0];
    const int*   amask = (const int*)  d_in[1];
    const float* Wq    = (const float*)d_in[2];
    const float* Wk    = (const float*)d_in[3];
    const float* Wv    = (const float*)d_in[4];
    const float* Wo    = (const float*)d_in[5];
    const float* bo    = (const float*)d_in[6];
    float*       out   = (float*)d_out;

    float *qkv, *ao;
    __nv_bfloat16 *ahi, *alo, *whi, *wlo;
    cudaGetSymbolAddress((void**)&qkv, g_qkv);
    cudaGetSymbolAddress((void**)&ao,  g_ao);
    cudaGetSymbolAddress((void**)&ahi, g_ahi);
    cudaGetSymbolAddress((void**)&alo, g_alo);
    cudaGetSymbolAddress((void**)&whi, g_whi);
    cudaGetSymbolAddress((void**)&wlo, g_wlo);

    cudaFuncSetAttribute(gemm_bf16x3_kernel,
                         cudaFuncAttributeMaxDynamicSharedMemorySize, GSMEM_TOTAL);
    cudaFuncSetAttribute(attn_local_kernel,
                         cudaFuncAttributeMaxDynamicSharedMemorySize, ATT_SMEM_BYTES);

    const int n4 = MROWS * DD / 4;

    split_kernel<<<(n4 + 255) / 256, 256>>>(hs, ahi, alo, n4);
    dim3 wgrid3(DD / 32, DD / 32, 3);
    wsplit3_kernel<<<wgrid3, 256>>>(Wq, Wk, Wv, whi, wlo);

    dim3 qkvgrid(3 * DD / 128, MROWS / 128);    // (48, 32)
    gemm_bf16x3_kernel<<<qkvgrid, 256, GSMEM_TOTAL>>>(ahi, alo, whi, wlo, nullptr, qkv);

    dim3 wgrid1(DD / 32, DD / 32, 1);
    wsplit3_kernel<<<wgrid1, 256>>>(Wo, Wo, Wo, whi, wlo);

    dim3 attn_grid(SS / BQ, HH, BB);            // (32, 16, 2)
    attn_local_kernel<<<attn_grid, 256, ATT_SMEM_BYTES>>>(
        qkv, qkv + MD, qkv + 2 * MD, amask, ao, ahi, alo);

    dim3 ogrid(DD / 128, MROWS / 128);          // (16, 32)
    gemm_bf16x3_kernel<<<ogrid, 256, GSMEM_TOTAL>>>(ahi, alo, whi, wlo, bo, out);
}